// round 1
// baseline (speedup 1.0000x reference)
#include <cuda_runtime.h>
#include <cstdint>

#define NB   1024
#define TT   48
#define NPGc 32
#define FFc  5
#define HHc  512
#define EPGc 256
#define NTOT (NB*TT*NPGc)        // 1572864 nodes
#define ETOT (NB*TT*EPGc)        // 12582912 edges
#define NGRAPH (NB*TT)           // 49152 graphs
#define BH   (NB*HHc)            // 524288
#define SEQW (NPGc*FFc)          // 160
#define TSEQ (TT*SEQW)           // 7680

// ---------------- scratch (static device globals: no allocation in kernel_launch) ----
__device__ __align__(128) float g_y  [NTOT*FFc];     // ChebConv output [N,5]
__device__ __align__(128) float g_seq[NB*TSEQ];      // BN+sigmoid -> LSTM input [B,T,160]
__device__ __align__(128) float g_c  [BH];           // LSTM cell state [B,H]
__device__ __align__(128) float g_hs [TT*BH];        // LSTM hidden states [T,B,H]

__device__ __forceinline__ float sigmf(float x){ return 1.f/(1.f+__expf(-x)); }
__device__ __forceinline__ uint32_t f2tf32(float x){
    uint32_t u; asm("cvt.rna.tf32.f32 %0, %1;" : "=r"(u) : "f"(x)); return u;
}
__device__ __forceinline__ void mma_tf32(float* d, const uint32_t* a, const uint32_t* b){
    asm volatile("mma.sync.aligned.m16n8k8.row.col.f32.tf32.tf32.f32 "
        "{%0,%1,%2,%3}, {%4,%5,%6,%7}, {%8,%9}, {%0,%1,%2,%3};"
        : "+f"(d[0]), "+f"(d[1]), "+f"(d[2]), "+f"(d[3])
        : "r"(a[0]), "r"(a[1]), "r"(a[2]), "r"(a[3]), "r"(b[0]), "r"(b[1]));
}

// ==================== Kernel 1: fused per-graph ChebConv (K=3) =======================
// One block = one 32-node / 256-edge graph, entirely in shared memory.
__global__ __launch_bounds__(256) void cheb_kernel(
    const float* __restrict__ x, const float* __restrict__ ea,
    const int* __restrict__ ei, const float* __restrict__ cw,
    const float* __restrict__ cb)
{
    __shared__ float sx[160], st1[160], st2[160];
    __shared__ float sdeg[32], sdinv[32];
    __shared__ float sW[75], sb[5];
    const int g  = blockIdx.x;
    const int nb = g * NPGc;
    const int tid = threadIdx.x;

    if (tid < 160){ sx[tid] = x[nb*FFc + tid]; st1[tid] = 0.f; st2[tid] = 0.f; }
    if (tid < 75)  sW[tid] = cw[tid];
    if (tid < 5)   sb[tid] = cb[tid];
    if (tid < 32)  sdeg[tid] = 0.f;
    __syncthreads();

    const int e = g * EPGc + tid;
    const int s = ei[e]        - nb;   // src local
    const int d = ei[ETOT + e] - nb;   // dst local
    const float w = ea[e];
    atomicAdd(&sdeg[s], w);
    __syncthreads();

    if (tid < 32) sdinv[tid] = (sdeg[tid] > 0.f) ? rsqrtf(sdeg[tid]) : 0.f;
    __syncthreads();

    const float nrm = -sdinv[s] * w * sdinv[d];
    // T1 = L~ x
    #pragma unroll
    for (int f = 0; f < FFc; ++f) atomicAdd(&st1[d*FFc + f], nrm * sx[s*FFc + f]);
    __syncthreads();
    // raw = L~ T1 ; T2 = 2*raw - x
    #pragma unroll
    for (int f = 0; f < FFc; ++f) atomicAdd(&st2[d*FFc + f], nrm * st1[s*FFc + f]);
    __syncthreads();

    if (tid < 160){
        const int p = tid / FFc, j = tid - p*FFc;
        float o = sb[j];
        #pragma unroll
        for (int i = 0; i < FFc; ++i){
            const float x0 = sx [p*FFc + i];
            const float t1 = st1[p*FFc + i];
            const float t2 = 2.f*st2[p*FFc + i] - x0;
            o += x0*sW[i*5+j] + t1*sW[25 + i*5+j] + t2*sW[50 + i*5+j];
        }
        g_y[nb*FFc + tid] = o;
    }
}

// ==================== Kernel 2: per-sample BatchNorm + sigmoid =======================
__global__ __launch_bounds__(256) void bn_kernel(
    const float* __restrict__ gamma, const float* __restrict__ beta)
{
    const int b = blockIdx.x, tid = threadIdx.x;
    const float* yb = g_y + (size_t)b * TSEQ;
    float s[5] = {0,0,0,0,0}, q[5] = {0,0,0,0,0};
    for (int nidx = tid; nidx < TT*NPGc; nidx += 256){
        const float* p = yb + nidx*FFc;
        #pragma unroll
        for (int f = 0; f < 5; ++f){ float v = p[f]; s[f] += v; q[f] += v*v; }
    }
    __shared__ float rs[5][257], rq[5][257];
    #pragma unroll
    for (int f = 0; f < 5; ++f){ rs[f][tid] = s[f]; rq[f][tid] = q[f]; }
    __syncthreads();
    for (int st = 128; st > 0; st >>= 1){
        if (tid < st){
            #pragma unroll
            for (int f = 0; f < 5; ++f){ rs[f][tid] += rs[f][tid+st]; rq[f][tid] += rq[f][tid+st]; }
        }
        __syncthreads();
    }
    __shared__ float sc[5], sh[5];
    if (tid < 5){
        const float inv = 1.f / (float)(TT*NPGc);
        const float mean = rs[tid][0] * inv;
        const float var  = rq[tid][0] * inv - mean*mean;
        const float scl  = gamma[tid] * rsqrtf(var + 1e-5f);
        sc[tid] = scl; sh[tid] = beta[tid] - mean*scl;
    }
    __syncthreads();
    float* ob = g_seq + (size_t)b * TSEQ;
    for (int nidx = tid; nidx < TT*NPGc; nidx += 256){
        const float* p = yb + nidx*FFc;
        #pragma unroll
        for (int f = 0; f < 5; ++f) ob[nidx*FFc + f] = sigmf(p[f]*sc[f] + sh[f]);
    }
}

// ==================== Kernel 3: fused LSTM step (tf32 mma) ===========================
// gates[b, g*512+h] = h_prev @ W_hh^T + seq_t @ W_ih^T + b_ih + b_hh, then cell update.
// Block tile: 64 batch-rows x 16 h-cols, replicated across the 4 gate regions.
__global__ __launch_bounds__(128) void lstm_step_kernel(
    int t,
    const float* __restrict__ Whh, const float* __restrict__ Wih,
    const float* __restrict__ bih, const float* __restrict__ bhh)
{
    __shared__ uint32_t As[64*20], Bs[64*20];
    __shared__ float sbias[64];
    const int tid  = threadIdx.x;
    const int lane = tid & 31, warp = tid >> 5;
    const int wm = warp & 1, wn = warp >> 1;
    const int hbase = blockIdx.x * 16;
    const int mbase = blockIdx.y * 64;
    const bool first = (t == 0);
    const float* h_in = g_hs + (size_t)(first ? 0 : (t-1)) * BH;
    float* h_out = g_hs + (size_t)t * BH;

    if (tid < 64){
        const int gg = tid >> 4, cc = tid & 15;
        sbias[tid] = bih[gg*HHc + hbase + cc] + bhh[gg*HHc + hbase + cc];
    }

    float acc[2][4][4];
    #pragma unroll
    for (int a=0;a<2;a++)
      #pragma unroll
      for (int b=0;b<4;b++)
        #pragma unroll
        for (int c=0;c<4;c++) acc[a][b][c]=0.f;

    const int nkt1 = first ? 0 : 32;          // K=512 recurrent phase
    const int nkt  = nkt1 + 10;               // +K=160 input phase
    for (int kt = 0; kt < nkt; ++kt){
        const float* Ag; const float* Bg; int lda, ldb;
        if (kt < nkt1){
            const int k0 = kt*16;
            Ag = h_in + (size_t)mbase*HHc + k0; lda = HHc;
            Bg = Whh + k0;                      ldb = HHc;
        } else {
            const int k0 = (kt - nkt1)*16;
            Ag = g_seq + (size_t)mbase*TSEQ + t*SEQW + k0; lda = TSEQ;
            Bg = Wih + k0;                                 ldb = SEQW;
        }
        __syncthreads();
        #pragma unroll
        for (int j = 0; j < 2; ++j){
            const int q = tid + j*128;
            const int r = q >> 2, c = (q & 3) * 4;
            float4 av = *(const float4*)(Ag + (size_t)r*lda + c);
            As[r*20+c+0]=f2tf32(av.x); As[r*20+c+1]=f2tf32(av.y);
            As[r*20+c+2]=f2tf32(av.z); As[r*20+c+3]=f2tf32(av.w);
            const int wrow = (r >> 4)*HHc + hbase + (r & 15);
            float4 bv = *(const float4*)(Bg + (size_t)wrow*ldb + c);
            Bs[r*20+c+0]=f2tf32(bv.x); Bs[r*20+c+1]=f2tf32(bv.y);
            Bs[r*20+c+2]=f2tf32(bv.z); Bs[r*20+c+3]=f2tf32(bv.w);
        }
        __syncthreads();
        const int gl = lane >> 2, tl = lane & 3;
        #pragma unroll
        for (int kk = 0; kk < 16; kk += 8){
            uint32_t a[2][4];
            #pragma unroll
            for (int mf = 0; mf < 2; ++mf){
                const int ar = wm*32 + mf*16 + gl;
                a[mf][0] = As[ ar   *20 + kk + tl];
                a[mf][1] = As[(ar+8)*20 + kk + tl];
                a[mf][2] = As[ ar   *20 + kk + tl + 4];
                a[mf][3] = As[(ar+8)*20 + kk + tl + 4];
            }
            #pragma unroll
            for (int gq = 0; gq < 4; ++gq){
                uint32_t bfr[2];
                const int br = gq*16 + wn*8 + gl;
                bfr[0] = Bs[br*20 + kk + tl];
                bfr[1] = Bs[br*20 + kk + tl + 4];
                mma_tf32(acc[0][gq], a[0], bfr);
                mma_tf32(acc[1][gq], a[1], bfr);
            }
        }
    }

    // epilogue: gate nonlinearities + cell/hidden update
    const int gl = lane >> 2, tl = lane & 3;
    #pragma unroll
    for (int mf = 0; mf < 2; ++mf){
        const int r0 = mbase + wm*32 + mf*16 + gl;
        const int cl = wn*8 + 2*tl;
        #pragma unroll
        for (int half = 0; half < 2; ++half){
            const int r = r0 + half*8;
            #pragma unroll
            for (int j = 0; j < 2; ++j){
                const int c = cl + j;
                const int col = hbase + c;
                const int ai = half*2 + j;
                const float iv = acc[mf][0][ai] + sbias[c];
                const float fv = acc[mf][1][ai] + sbias[16 + c];
                const float gv = acc[mf][2][ai] + sbias[32 + c];
                const float ov = acc[mf][3][ai] + sbias[48 + c];
                const float ii = sigmf(iv), ffv = sigmf(fv);
                const float gg = tanhf(gv),  oo = sigmf(ov);
                const int off = r*HHc + col;
                const float cold = first ? 0.f : g_c[off];
                const float cn = ffv*cold + ii*gg;
                g_c[off]   = cn;
                h_out[off] = oo * tanhf(cn);
            }
        }
    }
}

// ==================== Kernel 4: final linear over sigmoid(hs) ========================
__global__ __launch_bounds__(256) void final_kernel(
    const float* __restrict__ linW, const float* __restrict__ linb,
    float* __restrict__ outp)
{
    const int b = blockIdx.x, tid = threadIdx.x;
    float acc[4] = {0,0,0,0};
    for (int idx = tid; idx < TT*HHc; idx += 256){
        const int tq = idx >> 9, h = idx & 511;
        const float v = sigmf(g_hs[(size_t)tq*BH + b*HHc + h]);
        #pragma unroll
        for (int o = 0; o < 4; ++o) acc[o] += v * linW[o*(TT*HHc) + idx];
    }
    __shared__ float red[256];
    #pragma unroll
    for (int o = 0; o < 4; ++o){
        red[tid] = acc[o]; __syncthreads();
        for (int st = 128; st > 0; st >>= 1){
            if (tid < st) red[tid] += red[tid+st];
            __syncthreads();
        }
        if (tid == 0) outp[b*4 + o] = sigmf(red[0] + linb[o]);
        __syncthreads();
    }
}

// =====================================================================================
extern "C" void kernel_launch(void* const* d_in, const int* in_sizes, int n_in,
                              void* d_out, int out_size)
{
    const float* x     = (const float*)d_in[0];
    const float* ea    = (const float*)d_in[1];
    const float* cw    = (const float*)d_in[2];
    const float* cb    = (const float*)d_in[3];
    const float* gamma = (const float*)d_in[4];
    const float* beta  = (const float*)d_in[5];
    const float* Wih   = (const float*)d_in[6];
    const float* Whh   = (const float*)d_in[7];
    const float* bih   = (const float*)d_in[8];
    const float* bhh   = (const float*)d_in[9];
    const float* linW  = (const float*)d_in[10];
    const float* linb  = (const float*)d_in[11];
    const int*   ei    = (const int*)  d_in[12];
    float* outp = (float*)d_out;

    cheb_kernel<<<NGRAPH, 256>>>(x, ea, ei, cw, cb);
    bn_kernel<<<NB, 256>>>(gamma, beta);
    for (int t = 0; t < TT; ++t){
        lstm_step_kernel<<<dim3(HHc/16, NB/64), 128>>>(t, Whh, Wih, bih, bhh);
    }
    final_kernel<<<NB, 256>>>(linW, linb, outp);
}

// round 2
// speedup vs baseline: 2.0933x; 2.0933x over previous
#include <cuda_runtime.h>
#include <cuda_fp16.h>
#include <cstdint>

#define NB   1024
#define TT   48
#define NPGc 32
#define FFc  5
#define HHc  512
#define EPGc 256
#define NTOT (NB*TT*NPGc)
#define ETOT (NB*TT*EPGc)
#define NGRAPH (NB*TT)
#define BH   (NB*HHc)
#define SEQW (NPGc*FFc)          // 160
#define TSEQ (TT*SEQW)           // 7680
#define KTOT 672                 // 512 + 160 combined K
#define SLOT ((size_t)NB*KTOT)   // per-t activation slot (half elems)
#define NKT  42                  // 672/16

// ---------------- static device scratch --------------------------------------------
__device__ __align__(128) float  g_y  [NTOT*FFc];        // ChebConv out [N,5]
__device__ __align__(128) __half g_hx [49*NB*KTOT];      // [t][B][ h_{t-1}(512) | seq_t(160) ]
__device__ __align__(128) float  g_c  [BH];              // LSTM cell state
__device__ __align__(128) __half g_Wc [4*HHc*KTOT];      // packed [Whh|Wih] half, block-perm rows
__device__ __align__(128) float  g_bc [4*HHc];           // packed bias (bih+bhh)

__device__ __forceinline__ float sigmf(float x){ return 1.f/(1.f+__expf(-x)); }

__device__ __forceinline__ void cpasync16(void* dst, const void* src){
    uint32_t d = (uint32_t)__cvta_generic_to_shared(dst);
    asm volatile("cp.async.cg.shared.global [%0], [%1], 16;\n" :: "r"(d), "l"(src));
}
__device__ __forceinline__ void cp_commit(){ asm volatile("cp.async.commit_group;\n"); }
__device__ __forceinline__ void cp_wait1(){ asm volatile("cp.async.wait_group 1;\n"); }

__device__ __forceinline__ void ldm_x4(uint32_t* r, const __half* p){
    uint32_t a = (uint32_t)__cvta_generic_to_shared(p);
    asm volatile("ldmatrix.sync.aligned.m8n8.x4.shared.b16 {%0,%1,%2,%3}, [%4];"
        : "=r"(r[0]), "=r"(r[1]), "=r"(r[2]), "=r"(r[3]) : "r"(a));
}
__device__ __forceinline__ void mma_f16(float* d, const uint32_t* a, const uint32_t* b){
    asm volatile("mma.sync.aligned.m16n8k16.row.col.f32.f16.f16.f32 "
        "{%0,%1,%2,%3}, {%4,%5,%6,%7}, {%8,%9}, {%0,%1,%2,%3};"
        : "+f"(d[0]), "+f"(d[1]), "+f"(d[2]), "+f"(d[3])
        : "r"(a[0]), "r"(a[1]), "r"(a[2]), "r"(a[3]), "r"(b[0]), "r"(b[1]));
}

// ==================== Kernel 0: pack weights + bias to half, block-friendly order ====
// packed row R: hblk = R>>7, within = R&127, g = within>>5, hloc = within&31
//   -> h = hblk*32+hloc, original row p = g*512+h ; cols: [0,512)=Whh, [512,672)=Wih
__global__ __launch_bounds__(256) void pack_kernel(
    const float* __restrict__ Wih, const float* __restrict__ Whh,
    const float* __restrict__ bih, const float* __restrict__ bhh)
{
    int idx = blockIdx.x*256 + threadIdx.x;
    const int total = 4*HHc*KTOT;
    for (; idx < total; idx += gridDim.x*256){
        const int R = idx / KTOT, k = idx - R*KTOT;
        const int hblk = R >> 7, within = R & 127;
        const int g = within >> 5, hloc = within & 31;
        const int p = g*HHc + hblk*32 + hloc;
        const float v = (k < HHc) ? Whh[(size_t)p*HHc + k] : Wih[(size_t)p*SEQW + (k-HHc)];
        g_Wc[idx] = __float2half(v);
        if (k == 0) g_bc[R] = bih[p] + bhh[p];
    }
}

// ==================== Kernel 1: fused per-graph ChebConv (K=3) =======================
__global__ __launch_bounds__(256) void cheb_kernel(
    const float* __restrict__ x, const float* __restrict__ ea,
    const int* __restrict__ ei, const float* __restrict__ cw,
    const float* __restrict__ cb)
{
    __shared__ float sx[160], st1[160], st2[160];
    __shared__ float sdeg[32], sdinv[32];
    __shared__ float sW[75], sb[5];
    const int g  = blockIdx.x;
    const int nb = g * NPGc;
    const int tid = threadIdx.x;

    if (tid < 160){ sx[tid] = x[nb*FFc + tid]; st1[tid] = 0.f; st2[tid] = 0.f; }
    if (tid < 75)  sW[tid] = cw[tid];
    if (tid < 5)   sb[tid] = cb[tid];
    if (tid < 32)  sdeg[tid] = 0.f;
    __syncthreads();

    const int e = g * EPGc + tid;
    const int s = ei[e]        - nb;
    const int d = ei[ETOT + e] - nb;
    const float w = ea[e];
    atomicAdd(&sdeg[s], w);
    __syncthreads();

    if (tid < 32) sdinv[tid] = (sdeg[tid] > 0.f) ? rsqrtf(sdeg[tid]) : 0.f;
    __syncthreads();

    const float nrm = -sdinv[s] * w * sdinv[d];
    #pragma unroll
    for (int f = 0; f < FFc; ++f) atomicAdd(&st1[d*FFc + f], nrm * sx[s*FFc + f]);
    __syncthreads();
    #pragma unroll
    for (int f = 0; f < FFc; ++f) atomicAdd(&st2[d*FFc + f], nrm * st1[s*FFc + f]);
    __syncthreads();

    if (tid < 160){
        const int p = tid / FFc, j = tid - p*FFc;
        float o = sb[j];
        #pragma unroll
        for (int i = 0; i < FFc; ++i){
            const float x0 = sx [p*FFc + i];
            const float t1 = st1[p*FFc + i];
            const float t2 = 2.f*st2[p*FFc + i] - x0;
            o += x0*sW[i*5+j] + t1*sW[25 + i*5+j] + t2*sW[50 + i*5+j];
        }
        g_y[nb*FFc + tid] = o;
    }
}

// ==================== Kernel 2: per-sample BN + sigmoid -> half seq into g_hx ========
__global__ __launch_bounds__(256) void bn_kernel(
    const float* __restrict__ gamma, const float* __restrict__ beta)
{
    const int b = blockIdx.x, tid = threadIdx.x;
    const float* yb = g_y + (size_t)b * TSEQ;
    float s[5] = {0,0,0,0,0}, q[5] = {0,0,0,0,0};
    for (int nidx = tid; nidx < TT*NPGc; nidx += 256){
        const float* p = yb + nidx*FFc;
        #pragma unroll
        for (int f = 0; f < 5; ++f){ float v = p[f]; s[f] += v; q[f] += v*v; }
    }
    __shared__ float rs[5][257], rq[5][257];
    #pragma unroll
    for (int f = 0; f < 5; ++f){ rs[f][tid] = s[f]; rq[f][tid] = q[f]; }
    __syncthreads();
    for (int st = 128; st > 0; st >>= 1){
        if (tid < st){
            #pragma unroll
            for (int f = 0; f < 5; ++f){ rs[f][tid] += rs[f][tid+st]; rq[f][tid] += rq[f][tid+st]; }
        }
        __syncthreads();
    }
    __shared__ float sc[5], sh[5];
    if (tid < 5){
        const float inv = 1.f / (float)(TT*NPGc);
        const float mean = rs[tid][0] * inv;
        const float var  = rq[tid][0] * inv - mean*mean;
        const float scl  = gamma[tid] * rsqrtf(var + 1e-5f);
        sc[tid] = scl; sh[tid] = beta[tid] - mean*scl;
    }
    __syncthreads();
    // zero h-region of slot 0 for this sample
    __half2* hz = (__half2*)(g_hx + (size_t)b*KTOT);
    for (int j = tid; j < HHc/2; j += 256) hz[j] = __half2half2(__float2half(0.f));
    // write sigmoid(bn(y)) as half into seq region of each t-slot
    for (int nidx = tid; nidx < TT*NPGc; nidx += 256){
        const int t = nidx >> 5, node = nidx & 31;
        const float* p = yb + nidx*FFc;
        __half* ob = g_hx + (size_t)t*SLOT + (size_t)b*KTOT + HHc + node*FFc;
        #pragma unroll
        for (int f = 0; f < 5; ++f) ob[f] = __float2half(sigmf(p[f]*sc[f] + sh[f]));
    }
}

// ==================== Kernel 3: LSTM step = fp16 GEMM + fused gate epilogue ==========
// C[1024 x 2048] = A[1024 x 672] @ Wc^T ; block tile: 128 rows x (32 h-cols x 4 gates)
#define ASTRIDE 24   // 16 data halfs + 8 pad (48B rows -> conflict-free ldmatrix)
__global__ __launch_bounds__(256, 1) void lstm_step_kernel(int t)
{
    __shared__ __half As [3][128*ASTRIDE];
    __shared__ __half Bsm[3][128*ASTRIDE];
    __shared__ float  sbias[128];

    const int tid  = threadIdx.x;
    const int lane = tid & 31, warp = tid >> 5;
    const int wm = warp >> 1, wn = warp & 1;           // 4 x 2 warp grid
    const int hblk  = blockIdx.x;                      // 16 h-blocks (32 h-cols each)
    const int mbase = blockIdx.y * 128;                // 8 m-blocks
    const bool first = (t == 0);

    const __half* Ag = g_hx + (size_t)t*SLOT + (size_t)mbase*KTOT;
    const __half* Bg = g_Wc + (size_t)(hblk*128)*KTOT;

    if (tid < 128) sbias[tid] = g_bc[hblk*128 + tid];

    const int arow = tid >> 1, apart = tid & 1;        // 256 threads: 128 rows x 2 parts
    auto load_stage = [&](int s, int kt){
        const int k0 = kt*16;
        cpasync16(&As [s][arow*ASTRIDE + apart*8], Ag + (size_t)arow*KTOT + k0 + apart*8);
        cpasync16(&Bsm[s][arow*ASTRIDE + apart*8], Bg + (size_t)arow*KTOT + k0 + apart*8);
    };

    float acc[2][4][2][4];
    #pragma unroll
    for (int a=0;a<2;a++)
      #pragma unroll
      for (int b=0;b<4;b++)
        #pragma unroll
        for (int c=0;c<2;c++)
          #pragma unroll
          for (int d=0;d<4;d++) acc[a][b][c][d]=0.f;

    load_stage(0, 0); cp_commit();
    load_stage(1, 1); cp_commit();

    // ldmatrix lane address offsets (computed once)
    const int a_row = lane & 15, a_off = (lane >> 4) * 8;
    const int b_row = (lane & 7) + ((lane >> 4) & 1) * 8, b_off = ((lane >> 3) & 1) * 8;

    for (int kt = 0; kt < NKT; ++kt){
        cp_wait1();
        __syncthreads();
        if (kt + 2 < NKT) load_stage((kt+2)%3, kt+2);
        cp_commit();

        const int s = kt % 3;
        uint32_t af[2][4];
        #pragma unroll
        for (int mf = 0; mf < 2; ++mf)
            ldm_x4(af[mf], &As[s][(wm*32 + mf*16 + a_row)*ASTRIDE + a_off]);
        uint32_t bf[4][4];
        #pragma unroll
        for (int g = 0; g < 4; ++g)
            ldm_x4(bf[g], &Bsm[s][(g*32 + wn*16 + b_row)*ASTRIDE + b_off]);
        #pragma unroll
        for (int mf = 0; mf < 2; ++mf)
            #pragma unroll
            for (int g = 0; g < 4; ++g){
                mma_f16(acc[mf][g][0], af[mf], bf[g] + 0);
                mma_f16(acc[mf][g][1], af[mf], bf[g] + 2);
            }
    }

    // epilogue: gates -> cell update -> h (half) into next slot
    const int gl = lane >> 2, tl = lane & 3;
    __half* h_out = g_hx + (size_t)(t+1)*SLOT;
    const int hbase = hblk * 32;
    #pragma unroll
    for (int mf = 0; mf < 2; ++mf){
        #pragma unroll
        for (int nf = 0; nf < 2; ++nf){
            const int hloc0 = wn*16 + nf*8 + tl*2;     // local h col (0..31), even
            const int col0  = hbase + hloc0;
            #pragma unroll
            for (int rr = 0; rr < 2; ++rr){
                const int row = mbase + wm*32 + mf*16 + gl + rr*8;
                float hv[2];
                float cv[2];
                #pragma unroll
                for (int j = 0; j < 2; ++j){
                    const int e = rr*2 + j;
                    const int hl = hloc0 + j;
                    const float iv = acc[mf][0][nf][e] + sbias[0*32 + hl];
                    const float fv = acc[mf][1][nf][e] + sbias[1*32 + hl];
                    const float gv = acc[mf][2][nf][e] + sbias[2*32 + hl];
                    const float ov = acc[mf][3][nf][e] + sbias[3*32 + hl];
                    const float cold = first ? 0.f : g_c[(size_t)row*HHc + col0 + j];
                    const float cn = sigmf(fv)*cold + sigmf(iv)*tanhf(gv);
                    cv[j] = cn;
                    hv[j] = sigmf(ov) * tanhf(cn);
                }
                *(float2*)(g_c + (size_t)row*HHc + col0) = make_float2(cv[0], cv[1]);
                *(__half2*)(h_out + (size_t)row*KTOT + col0) =
                    __halves2half2(__float2half(hv[0]), __float2half(hv[1]));
            }
        }
    }
}

// ==================== Kernel 4: final linear over sigmoid(hs) ========================
__global__ __launch_bounds__(256) void final_kernel(
    const float* __restrict__ linW, const float* __restrict__ linb,
    float* __restrict__ outp)
{
    const int b = blockIdx.x, tid = threadIdx.x;
    float acc[4] = {0,0,0,0};
    for (int idx = tid; idx < TT*HHc; idx += 256){
        const int tq = idx >> 9, h = idx & 511;
        const float v = sigmf(__half2float(g_hx[(size_t)(tq+1)*SLOT + (size_t)b*KTOT + h]));
        #pragma unroll
        for (int o = 0; o < 4; ++o) acc[o] += v * linW[(size_t)o*(TT*HHc) + idx];
    }
    __shared__ float red[256];
    #pragma unroll
    for (int o = 0; o < 4; ++o){
        red[tid] = acc[o]; __syncthreads();
        for (int st = 128; st > 0; st >>= 1){
            if (tid < st) red[tid] += red[tid+st];
            __syncthreads();
        }
        if (tid == 0) outp[b*4 + o] = sigmf(red[0] + linb[o]);
        __syncthreads();
    }
}

// =====================================================================================
extern "C" void kernel_launch(void* const* d_in, const int* in_sizes, int n_in,
                              void* d_out, int out_size)
{
    const float* x     = (const float*)d_in[0];
    const float* ea    = (const float*)d_in[1];
    const float* cw    = (const float*)d_in[2];
    const float* cb    = (const float*)d_in[3];
    const float* gamma = (const float*)d_in[4];
    const float* beta  = (const float*)d_in[5];
    const float* Wih   = (const float*)d_in[6];
    const float* Whh   = (const float*)d_in[7];
    const float* bih   = (const float*)d_in[8];
    const float* bhh   = (const float*)d_in[9];
    const float* linW  = (const float*)d_in[10];
    const float* linb  = (const float*)d_in[11];
    const int*   ei    = (const int*)  d_in[12];
    float* outp = (float*)d_out;

    pack_kernel<<<1024, 256>>>(Wih, Whh, bih, bhh);
    cheb_kernel<<<NGRAPH, 256>>>(x, ea, ei, cw, cb);
    bn_kernel<<<NB, 256>>>(gamma, beta);
    for (int t = 0; t < TT; ++t){
        lstm_step_kernel<<<dim3(16, 8), 256>>>(t);
    }
    final_kernel<<<NB, 256>>>(linW, linb, outp);
}

// round 4
// speedup vs baseline: 2.3278x; 1.1120x over previous
#include <cuda_runtime.h>
#include <cuda_fp16.h>
#include <cstdint>

#define NB   1024
#define TT   48
#define NPGc 32
#define FFc  5
#define HHc  512
#define EPGc 256
#define NTOT (NB*TT*NPGc)
#define ETOT (NB*TT*EPGc)
#define NGRAPH (NB*TT)
#define SEQW 160
#define TSEQ (TT*SEQW)
#define KTOT 672
#define KPAD 704                   // 11 chunks of 64
#define SLOT ((size_t)NB*KPAD)
#define NCHUNK 11

// dynamic smem layout
#define SOFF_BIAS 0                // 512 B
#define SOFF_A    1024             // 3 stages x 16384
#define SOFF_W    (1024 + 3*16384) // 11 chunks x 16384
#define SMEM_SZ   (SOFF_W + NCHUNK*16384)   // 230400 B

// ---------------- static device scratch --------------------------------------------
__device__ __align__(128) float  g_y  [NTOT*FFc];
__device__ __align__(128) __half g_hx [49*NB*KPAD];   // [t][B][ h(512) | seq(160) | pad(32) ]
__device__ __align__(128) __half g_Wc [4*HHc*KPAD];   // packed [Whh|Wih|0] half (row-permuted)
__device__ __align__(128) float  g_bc [4*HHc];
__device__ unsigned g_bar  = 0;
__device__ unsigned g_done = 0;

__device__ __forceinline__ float sigmf(float x){ return 1.f/(1.f+__expf(-x)); }

__device__ __forceinline__ void cpasync16(void* dst, const void* src){
    uint32_t d = (uint32_t)__cvta_generic_to_shared(dst);
    asm volatile("cp.async.cg.shared.global [%0], [%1], 16;\n" :: "r"(d), "l"(src));
}
__device__ __forceinline__ void cp_commit(){ asm volatile("cp.async.commit_group;\n"); }
template<int N> __device__ __forceinline__ void cp_wait(){
    asm volatile("cp.async.wait_group %0;\n" :: "n"(N));
}
__device__ __forceinline__ void ldm_x4(uint32_t* r, const void* p){
    uint32_t a = (uint32_t)__cvta_generic_to_shared(p);
    asm volatile("ldmatrix.sync.aligned.m8n8.x4.shared.b16 {%0,%1,%2,%3}, [%4];"
        : "=r"(r[0]), "=r"(r[1]), "=r"(r[2]), "=r"(r[3]) : "r"(a));
}
__device__ __forceinline__ void mma_f16(float* d, const uint32_t* a, const uint32_t* b){
    asm volatile("mma.sync.aligned.m16n8k16.row.col.f32.f16.f16.f32 "
        "{%0,%1,%2,%3}, {%4,%5,%6,%7}, {%8,%9}, {%0,%1,%2,%3};"
        : "+f"(d[0]), "+f"(d[1]), "+f"(d[2]), "+f"(d[3])
        : "r"(a[0]), "r"(a[1]), "r"(a[2]), "r"(a[3]), "r"(b[0]), "r"(b[1]));
}
__device__ __forceinline__ uint32_t swz(uint32_t off){ return off ^ ((off >> 3) & 0x70); }

// ==================== Kernel 0: pack weights (+bias) to half, padded K ===============
__global__ __launch_bounds__(256) void pack_kernel(
    const float* __restrict__ Wih, const float* __restrict__ Whh,
    const float* __restrict__ bih, const float* __restrict__ bhh)
{
    int idx = blockIdx.x*256 + threadIdx.x;
    const int total = 4*HHc*KPAD;
    for (; idx < total; idx += gridDim.x*256){
        const int R = idx / KPAD, k = idx - R*KPAD;
        const int hblk = R >> 7, within = R & 127;
        const int g = within >> 5, hloc = within & 31;
        const int p = g*HHc + hblk*32 + hloc;
        float v = 0.f;
        if (k < HHc)       v = Whh[(size_t)p*HHc + k];
        else if (k < KTOT) v = Wih[(size_t)p*SEQW + (k-HHc)];
        g_Wc[idx] = __float2half(v);
        if (k == 0) g_bc[R] = bih[p] + bhh[p];
    }
}

// ==================== Kernel 1: fused per-graph ChebConv (K=3) =======================
__global__ __launch_bounds__(256) void cheb_kernel(
    const float* __restrict__ x, const float* __restrict__ ea,
    const int* __restrict__ ei, const float* __restrict__ cw,
    const float* __restrict__ cb)
{
    __shared__ float sx[160], st1[160], st2[160];
    __shared__ float sdeg[32], sdinv[32];
    __shared__ float sW[75], sb[5];
    const int g  = blockIdx.x;
    const int nb = g * NPGc;
    const int tid = threadIdx.x;

    if (tid < 160){ sx[tid] = x[nb*FFc + tid]; st1[tid] = 0.f; st2[tid] = 0.f; }
    if (tid < 75)  sW[tid] = cw[tid];
    if (tid < 5)   sb[tid] = cb[tid];
    if (tid < 32)  sdeg[tid] = 0.f;
    __syncthreads();

    const int e = g * EPGc + tid;
    const int s = ei[e]        - nb;
    const int d = ei[ETOT + e] - nb;
    const float w = ea[e];
    atomicAdd(&sdeg[s], w);
    __syncthreads();

    if (tid < 32) sdinv[tid] = (sdeg[tid] > 0.f) ? rsqrtf(sdeg[tid]) : 0.f;
    __syncthreads();

    const float nrm = -sdinv[s] * w * sdinv[d];
    #pragma unroll
    for (int f = 0; f < FFc; ++f) atomicAdd(&st1[d*FFc + f], nrm * sx[s*FFc + f]);
    __syncthreads();
    #pragma unroll
    for (int f = 0; f < FFc; ++f) atomicAdd(&st2[d*FFc + f], nrm * st1[s*FFc + f]);
    __syncthreads();

    if (tid < 160){
        const int p = tid / FFc, j = tid - p*FFc;
        float o = sb[j];
        #pragma unroll
        for (int i = 0; i < FFc; ++i){
            const float x0 = sx [p*FFc + i];
            const float t1 = st1[p*FFc + i];
            const float t2 = 2.f*st2[p*FFc + i] - x0;
            o += x0*sW[i*5+j] + t1*sW[25 + i*5+j] + t2*sW[50 + i*5+j];
        }
        g_y[nb*FFc + tid] = o;
    }
}

// ==================== Kernel 2: per-sample BN + sigmoid -> half seq into g_hx ========
__global__ __launch_bounds__(256) void bn_kernel(
    const float* __restrict__ gamma, const float* __restrict__ beta)
{
    const int b = blockIdx.x, tid = threadIdx.x;
    const float* yb = g_y + (size_t)b * TSEQ;
    float s[5] = {0,0,0,0,0}, q[5] = {0,0,0,0,0};
    for (int nidx = tid; nidx < TT*NPGc; nidx += 256){
        const float* p = yb + nidx*FFc;
        #pragma unroll
        for (int f = 0; f < 5; ++f){ float v = p[f]; s[f] += v; q[f] += v*v; }
    }
    __shared__ float rs[5][257], rq[5][257];
    #pragma unroll
    for (int f = 0; f < 5; ++f){ rs[f][tid] = s[f]; rq[f][tid] = q[f]; }
    __syncthreads();
    for (int st = 128; st > 0; st >>= 1){
        if (tid < st){
            #pragma unroll
            for (int f = 0; f < 5; ++f){ rs[f][tid] += rs[f][tid+st]; rq[f][tid] += rq[f][tid+st]; }
        }
        __syncthreads();
    }
    __shared__ float sc[5], sh[5];
    if (tid < 5){
        const float inv = 1.f / (float)(TT*NPGc);
        const float mean = rs[tid][0] * inv;
        const float var  = rq[tid][0] * inv - mean*mean;
        const float scl  = gamma[tid] * rsqrtf(var + 1e-5f);
        sc[tid] = scl; sh[tid] = beta[tid] - mean*scl;
    }
    __syncthreads();
    // zero h-region of slot 0 for this sample
    __half2* hz = (__half2*)(g_hx + (size_t)b*KPAD);
    for (int j = tid; j < HHc/2; j += 256) hz[j] = __half2half2(__float2half(0.f));
    // zero K padding [672,704) for all t-slots of this sample
    for (int j = tid; j < TT*(KPAD-KTOT); j += 256){
        const int t = j / (KPAD-KTOT), c = j % (KPAD-KTOT);
        g_hx[(size_t)t*SLOT + (size_t)b*KPAD + KTOT + c] = __float2half(0.f);
    }
    // write sigmoid(bn(y)) as half into seq region of each t-slot
    for (int nidx = tid; nidx < TT*NPGc; nidx += 256){
        const int t = nidx >> 5, node = nidx & 31;
        const float* p = yb + nidx*FFc;
        __half* ob = g_hx + (size_t)t*SLOT + (size_t)b*KPAD + HHc + node*FFc;
        #pragma unroll
        for (int f = 0; f < 5; ++f) ob[f] = __float2half(sigmf(p[f]*sc[f] + sh[f]));
    }
}

// ==================== Kernel 3: persistent LSTM (all 48 steps, W resident) ===========
// grid (16 hblk, 8 mblk), 256 threads. Block tile: 128 rows x 128 cols (4 gates x 32 h).
__global__ __launch_bounds__(256, 1) void lstm_persist_kernel()
{
    extern __shared__ char smem[];
    float* sbias = (float*)(smem + SOFF_BIAS);
    char*  Asm   = smem + SOFF_A;
    char*  Wsm   = smem + SOFF_W;

    const int tid  = threadIdx.x;
    const int lane = tid & 31, warp = tid >> 5;
    const int wm = warp >> 1, wn = warp & 1;          // 4 x 2 warp grid
    const int hblk  = blockIdx.x;
    const int mbase = blockIdx.y * 128;
    const int hbase = hblk * 32;

    // ---- load weight tile (128 x 704 half) into swizzled smem chunks, once ----
    const __half* Bg = g_Wc + (size_t)(hblk*128)*KPAD;
    for (int i = tid; i < 128*NCHUNK*8; i += 256){      // 16B pieces
        const int r = i / (NCHUNK*8);
        const int rem = i - r*(NCHUNK*8);
        const int c = rem >> 3, j = rem & 7;
        cpasync16(Wsm + c*16384 + swz((uint32_t)r*128 + j*16),
                  Bg + (size_t)r*KPAD + c*64 + j*8);
    }
    if (tid < 128) sbias[tid] = g_bc[hblk*128 + tid];
    cp_commit();

    // A stage fill: chunk (64 K-cols) -> stage
    auto fillA = [&](int chunk, int stage, const __half* Ag){
        char* dst = Asm + stage*16384;
        const __half* src = Ag + chunk*64;
        #pragma unroll
        for (int p = 0; p < 4; ++p){
            const int idx = tid + p*256;
            const int r = idx >> 3, j = idx & 7;
            cpasync16(dst + swz((uint32_t)r*128 + j*16), src + (size_t)r*KPAD + j*8);
        }
        cp_commit();
    };

    // bootstrap: prefetch seq chunks (8,9,10) of step 0
    {
        const __half* Ag0 = g_hx + (size_t)mbase*KPAD;
        fillA(8, 0, Ag0); fillA(9, 1, Ag0); fillA(10, 2, Ag0);
    }

    float c_reg[2][2][4];
    #pragma unroll
    for (int a=0;a<2;a++) for (int b=0;b<2;b++) for (int e=0;e<4;e++) c_reg[a][b][e]=0.f;

    const int gl = lane >> 2, tl = lane & 3;

    for (int t = 0; t < TT; ++t){
        const __half* Ag = g_hx + (size_t)t*SLOT + (size_t)mbase*KPAD;

        float acc[2][4][2][4];
        #pragma unroll
        for (int a=0;a<2;a++) for (int b=0;b<4;b++) for (int c=0;c<2;c++)
            #pragma unroll
            for (int d=0;d<4;d++) acc[a][b][c][d]=0.f;

        // compute chunks in rotated order: 8,9,10,0,1,...,7
        for (int q = 0; q < NCHUNK; ++q){
            if (q <= 8) cp_wait<2>(); else if (q == 9) cp_wait<1>(); else cp_wait<0>();
            __syncthreads();
            const int c = (q < 3) ? q + 8 : q - 3;
            const char* Wc = Wsm + c*16384;
            const char* Ac = Asm + (q%3)*16384;
            #pragma unroll
            for (int kk = 0; kk < 4; ++kk){
                uint32_t af[2][4];
                #pragma unroll
                for (int mf = 0; mf < 2; ++mf){
                    const uint32_t off = (uint32_t)(wm*32 + mf*16 + (lane&15))*128
                                       + (uint32_t)(kk*16 + ((lane>>4)<<3))*2;
                    ldm_x4(af[mf], Ac + swz(off));
                }
                uint32_t bf[4][4];
                #pragma unroll
                for (int g = 0; g < 4; ++g){
                    const uint32_t off = (uint32_t)(g*32 + wn*16 + (lane&7) + ((lane>>4)&1)*8)*128
                                       + (uint32_t)(kk*16 + ((lane>>3)&1)*8)*2;
                    ldm_x4(bf[g], Wc + swz(off));
                }
                #pragma unroll
                for (int mf = 0; mf < 2; ++mf)
                    #pragma unroll
                    for (int g = 0; g < 4; ++g){
                        mma_f16(acc[mf][g][0], af[mf], bf[g] + 0);
                        mma_f16(acc[mf][g][1], af[mf], bf[g] + 2);
                    }
            }
            if (q < 8){
                __syncthreads();
                fillA(q, q%3, Ag);    // feeds iteration q+3 (stage q%3)
            }
        }
        __syncthreads();   // all warps done with stages before prefetch overwrites

        // prefetch seq chunks of step t+1 (independent of h); overlaps epilogue+barrier
        if (t + 1 < TT){
            const __half* Agn = g_hx + (size_t)(t+1)*SLOT + (size_t)mbase*KPAD;
            fillA(8, 0, Agn); fillA(9, 1, Agn); fillA(10, 2, Agn);
        }

        // epilogue: gates -> c (regs) -> h (half) into slot t+1
        __half* h_out = g_hx + (size_t)(t+1)*SLOT;
        #pragma unroll
        for (int mf = 0; mf < 2; ++mf){
            #pragma unroll
            for (int nf = 0; nf < 2; ++nf){
                const int hloc0 = wn*16 + nf*8 + tl*2;
                #pragma unroll
                for (int rr = 0; rr < 2; ++rr){
                    const int row = mbase + wm*32 + mf*16 + gl + rr*8;
                    float hv[2];
                    #pragma unroll
                    for (int j = 0; j < 2; ++j){
                        const int e = rr*2 + j;
                        const int hl = hloc0 + j;
                        const float iv = acc[mf][0][nf][e] + sbias[hl];
                        const float fv = acc[mf][1][nf][e] + sbias[32 + hl];
                        const float gv = acc[mf][2][nf][e] + sbias[64 + hl];
                        const float ov = acc[mf][3][nf][e] + sbias[96 + hl];
                        const float cn = sigmf(fv)*c_reg[mf][nf][e] + sigmf(iv)*tanhf(gv);
                        c_reg[mf][nf][e] = cn;
                        hv[j] = sigmf(ov)*tanhf(cn);
                    }
                    *(__half2*)(h_out + (size_t)row*KPAD + hbase + hloc0) =
                        __halves2half2(__float2half(hv[0]), __float2half(hv[1]));
                }
            }
        }

        // grid barrier between steps (monotone counter; all 128 blocks resident)
        if (t + 1 < TT){
            __threadfence();
            __syncthreads();
            if (tid == 0){
                atomicAdd(&g_bar, 1u);
                const unsigned target = 128u*(unsigned)(t+1);
                unsigned v;
                do {
                    asm volatile("ld.global.cg.u32 %0, [%1];" : "=r"(v) : "l"(&g_bar));
                } while (v < target);
                __threadfence();
            }
            __syncthreads();
        }
    }

    // reset barrier counters for the next launch (last block to finish does it)
    __syncthreads();
    if (tid == 0){
        const unsigned d = atomicAdd(&g_done, 1u);
        if (d == 127u){ g_bar = 0u; g_done = 0u; __threadfence(); }
    }
}

// ==================== Kernel 4: final linear over sigmoid(hs) ========================
__global__ __launch_bounds__(256) void final_kernel(
    const float* __restrict__ linW, const float* __restrict__ linb,
    float* __restrict__ outp)
{
    const int b = blockIdx.x, tid = threadIdx.x;
    float acc[4] = {0,0,0,0};
    for (int idx = tid; idx < TT*HHc; idx += 256){
        const int tq = idx >> 9, h = idx & 511;
        const float v = sigmf(__half2float(g_hx[(size_t)(tq+1)*SLOT + (size_t)b*KPAD + h]));
        #pragma unroll
        for (int o = 0; o < 4; ++o) acc[o] += v * linW[(size_t)o*(TT*HHc) + idx];
    }
    __shared__ float red[256];
    #pragma unroll
    for (int o = 0; o < 4; ++o){
        red[tid] = acc[o]; __syncthreads();
        for (int st = 128; st > 0; st >>= 1){
            if (tid < st) red[tid] += red[tid+st];
            __syncthreads();
        }
        if (tid == 0) outp[b*4 + o] = sigmf(red[0] + linb[o]);
        __syncthreads();
    }
}

// =====================================================================================
extern "C" void kernel_launch(void* const* d_in, const int* in_sizes, int n_in,
                              void* d_out, int out_size)
{
    const float* x     = (const float*)d_in[0];
    const float* ea    = (const float*)d_in[1];
    const float* cw    = (const float*)d_in[2];
    const float* cb    = (const float*)d_in[3];
    const float* gamma = (const float*)d_in[4];
    const float* beta  = (const float*)d_in[5];
    const float* Wih   = (const float*)d_in[6];
    const float* Whh   = (const float*)d_in[7];
    const float* bih   = (const float*)d_in[8];
    const float* bhh   = (const float*)d_in[9];
    const float* linW  = (const float*)d_in[10];
    const float* linb  = (const float*)d_in[11];
    const int*   ei    = (const int*)  d_in[12];
    float* outp = (float*)d_out;

    cudaFuncSetAttribute(lstm_persist_kernel,
        cudaFuncAttributeMaxDynamicSharedMemorySize, SMEM_SZ);

    pack_kernel<<<1024, 256>>>(Wih, Whh, bih, bhh);
    cheb_kernel<<<NGRAPH, 256>>>(x, ea, ei, cw, cb);
    bn_kernel<<<NB, 256>>>(gamma, beta);
    lstm_persist_kernel<<<dim3(16, 8), 256, SMEM_SZ>>>();
    final_kernel<<<NB, 256>>>(linW, linb, outp);
}

// round 5
// speedup vs baseline: 2.8019x; 1.2037x over previous
#include <cuda_runtime.h>
#include <cuda_fp16.h>
#include <cstdint>

#define NB   1024
#define TT   48
#define NPGc 32
#define FFc  5
#define HHc  512
#define EPGc 256
#define NTOT (NB*TT*NPGc)
#define ETOT (NB*TT*EPGc)
#define NGRAPH (NB*TT)
#define SEQW 160
#define TSEQ (TT*SEQW)
#define KTOT 672
#define KPAD 704                   // 11 chunks of 64
#define SLOT ((size_t)NB*KPAD)
#define NCHUNK 11

// dynamic smem layout for lstm kernel
#define SOFF_BIAS 0                // 512 B
#define SOFF_A    1024             // 3 stages x 16384
#define SOFF_W    (1024 + 3*16384) // 11 chunks x 16384
#define SMEM_SZ   (SOFF_W + NCHUNK*16384)   // 230400 B

// ---------------- static device scratch --------------------------------------------
__device__ __align__(128) float  g_y  [NTOT*FFc];
__device__ __align__(128) __half g_hx [49*NB*KPAD];   // [t][B][ h(512) | seq(160) | pad(32) ]
__device__ __align__(128) __half g_Wc [4*HHc*KPAD];   // packed [Whh|Wih|0] half (row-permuted)
__device__ __align__(128) float  g_bc [4*HHc];
__device__ __align__(128) unsigned g_flag[8][16];     // [mgrp][hblk] step counters
__device__ unsigned g_done = 0;

__device__ __forceinline__ float sigmf(float x){ return __fdividef(1.f, 1.f + __expf(-x)); }
__device__ __forceinline__ float tanhfast(float x){
    const float e = __expf(2.f*x);
    return 1.f - __fdividef(2.f, e + 1.f);
}

__device__ __forceinline__ void cpasync16(void* dst, const void* src){
    uint32_t d = (uint32_t)__cvta_generic_to_shared(dst);
    asm volatile("cp.async.cg.shared.global [%0], [%1], 16;\n" :: "r"(d), "l"(src));
}
__device__ __forceinline__ void cp_commit(){ asm volatile("cp.async.commit_group;\n"); }
template<int N> __device__ __forceinline__ void cp_wait(){
    asm volatile("cp.async.wait_group %0;\n" :: "n"(N));
}
__device__ __forceinline__ void ldm_x4(uint32_t* r, const void* p){
    uint32_t a = (uint32_t)__cvta_generic_to_shared(p);
    asm volatile("ldmatrix.sync.aligned.m8n8.x4.shared.b16 {%0,%1,%2,%3}, [%4];"
        : "=r"(r[0]), "=r"(r[1]), "=r"(r[2]), "=r"(r[3]) : "r"(a));
}
__device__ __forceinline__ void mma_f16(float* d, const uint32_t* a, const uint32_t* b){
    asm volatile("mma.sync.aligned.m16n8k16.row.col.f32.f16.f16.f32 "
        "{%0,%1,%2,%3}, {%4,%5,%6,%7}, {%8,%9}, {%0,%1,%2,%3};"
        : "+f"(d[0]), "+f"(d[1]), "+f"(d[2]), "+f"(d[3])
        : "r"(a[0]), "r"(a[1]), "r"(a[2]), "r"(a[3]), "r"(b[0]), "r"(b[1]));
}
__device__ __forceinline__ uint32_t swz(uint32_t off){ return off ^ ((off >> 3) & 0x70); }

// ==================== Kernel 0: pack weights (+bias) to half, padded K ===============
__global__ __launch_bounds__(256) void pack_kernel(
    const float* __restrict__ Wih, const float* __restrict__ Whh,
    const float* __restrict__ bih, const float* __restrict__ bhh)
{
    int idx = blockIdx.x*256 + threadIdx.x;
    const int total = 4*HHc*KPAD;
    for (; idx < total; idx += gridDim.x*256){
        const int R = idx / KPAD, k = idx - R*KPAD;
        const int hblk = R >> 7, within = R & 127;
        const int g = within >> 5, hloc = within & 31;
        const int p = g*HHc + hblk*32 + hloc;
        float v = 0.f;
        if (k < HHc)       v = Whh[(size_t)p*HHc + k];
        else if (k < KTOT) v = Wih[(size_t)p*SEQW + (k-HHc)];
        g_Wc[idx] = __float2half(v);
        if (k == 0) g_bc[R] = bih[p] + bhh[p];
    }
}

// ==================== Kernel 1: ChebConv — warp per graph, 8 graphs/block ============
__global__ __launch_bounds__(256) void cheb_kernel(
    const float* __restrict__ x, const float* __restrict__ ea,
    const int* __restrict__ ei, const float* __restrict__ cw,
    const float* __restrict__ cb)
{
    __shared__ float sx[8][160], st1[8][160], st2[8][160], sdeg[8][32];
    const int tid = threadIdx.x, lane = tid & 31, wid = tid >> 5;
    const int g  = blockIdx.x*8 + wid;
    const int nb = g * NPGc;
    float* SX  = sx[wid];
    float* ST1 = st1[wid];
    float* ST2 = st2[wid];
    float* SD  = sdeg[wid];

    #pragma unroll
    for (int r = 0; r < 5; ++r){
        SX [r*32 + lane] = x[(size_t)nb*FFc + r*32 + lane];
        ST1[r*32 + lane] = 0.f;
        ST2[r*32 + lane] = 0.f;
    }
    SD[lane] = 0.f;
    __syncwarp();

    int es[8], ed[8];
    float ew[8], nrm[8];
    #pragma unroll
    for (int r = 0; r < 8; ++r){
        const int e = g*EPGc + r*32 + lane;
        es[r] = ei[e]        - nb;
        ed[r] = ei[ETOT + e] - nb;
        ew[r] = ea[e];
        atomicAdd(&SD[es[r]], ew[r]);
    }
    __syncwarp();
    {
        float dv = SD[lane];
        dv = (dv > 0.f) ? rsqrtf(dv) : 0.f;
        __syncwarp();
        SD[lane] = dv;
    }
    __syncwarp();
    #pragma unroll
    for (int r = 0; r < 8; ++r) nrm[r] = -SD[es[r]] * ew[r] * SD[ed[r]];
    #pragma unroll
    for (int r = 0; r < 8; ++r){
        #pragma unroll
        for (int f = 0; f < FFc; ++f)
            atomicAdd(&ST1[ed[r]*FFc + f], nrm[r]*SX[es[r]*FFc + f]);
    }
    __syncwarp();
    #pragma unroll
    for (int r = 0; r < 8; ++r){
        #pragma unroll
        for (int f = 0; f < FFc; ++f)
            atomicAdd(&ST2[ed[r]*FFc + f], nrm[r]*ST1[es[r]*FFc + f]);
    }
    __syncwarp();

    // output: lane = node
    const int p = lane;
    float o[5];
    #pragma unroll
    for (int j = 0; j < 5; ++j) o[j] = __ldg(&cb[j]);
    #pragma unroll
    for (int i = 0; i < 5; ++i){
        const float x0 = SX [p*FFc + i];
        const float t1 = ST1[p*FFc + i];
        const float t2 = 2.f*ST2[p*FFc + i] - x0;
        #pragma unroll
        for (int j = 0; j < 5; ++j)
            o[j] += x0*__ldg(&cw[i*5+j]) + t1*__ldg(&cw[25+i*5+j]) + t2*__ldg(&cw[50+i*5+j]);
    }
    #pragma unroll
    for (int j = 0; j < 5; ++j) g_y[(size_t)nb*FFc + p*FFc + j] = o[j];
}

// ==================== Kernel 2: per-sample BN + sigmoid -> half seq into g_hx ========
__global__ __launch_bounds__(256) void bn_kernel(
    const float* __restrict__ gamma, const float* __restrict__ beta)
{
    const int b = blockIdx.x, tid = threadIdx.x;
    const float* yb = g_y + (size_t)b * TSEQ;
    float s[5] = {0,0,0,0,0}, q[5] = {0,0,0,0,0};
    for (int nidx = tid; nidx < TT*NPGc; nidx += 256){
        const float* p = yb + nidx*FFc;
        #pragma unroll
        for (int f = 0; f < 5; ++f){ float v = p[f]; s[f] += v; q[f] += v*v; }
    }
    __shared__ float rs[5][257], rq[5][257];
    #pragma unroll
    for (int f = 0; f < 5; ++f){ rs[f][tid] = s[f]; rq[f][tid] = q[f]; }
    __syncthreads();
    for (int st = 128; st > 0; st >>= 1){
        if (tid < st){
            #pragma unroll
            for (int f = 0; f < 5; ++f){ rs[f][tid] += rs[f][tid+st]; rq[f][tid] += rq[f][tid+st]; }
        }
        __syncthreads();
    }
    __shared__ float sc[5], sh[5];
    if (tid < 5){
        const float inv = 1.f / (float)(TT*NPGc);
        const float mean = rs[tid][0] * inv;
        const float var  = rq[tid][0] * inv - mean*mean;
        const float scl  = gamma[tid] * rsqrtf(var + 1e-5f);
        sc[tid] = scl; sh[tid] = beta[tid] - mean*scl;
    }
    __syncthreads();
    __half2* hz = (__half2*)(g_hx + (size_t)b*KPAD);
    for (int j = tid; j < HHc/2; j += 256) hz[j] = __half2half2(__float2half(0.f));
    for (int j = tid; j < TT*(KPAD-KTOT); j += 256){
        const int t = j / (KPAD-KTOT), c = j % (KPAD-KTOT);
        g_hx[(size_t)t*SLOT + (size_t)b*KPAD + KTOT + c] = __float2half(0.f);
    }
    for (int nidx = tid; nidx < TT*NPGc; nidx += 256){
        const int t = nidx >> 5, node = nidx & 31;
        const float* p = yb + nidx*FFc;
        __half* ob = g_hx + (size_t)t*SLOT + (size_t)b*KPAD + HHc + node*FFc;
        #pragma unroll
        for (int f = 0; f < 5; ++f) ob[f] = __float2half(sigmf(p[f]*sc[f] + sh[f]));
    }
}

// ==================== Kernel 3: persistent LSTM, flag-synced =========================
__global__ __launch_bounds__(256, 1) void lstm_persist_kernel()
{
    extern __shared__ char smem[];
    float* sbias = (float*)(smem + SOFF_BIAS);
    char*  Asm   = smem + SOFF_A;
    char*  Wsm   = smem + SOFF_W;

    const int tid  = threadIdx.x;
    const int lane = tid & 31, warp = tid >> 5;
    const int wm = warp >> 1, wn = warp & 1;          // 4 x 2 warp grid
    const int hblk  = blockIdx.x;                     // 16
    const int mgrp  = blockIdx.y;                     // 8
    const int mbase = mgrp * 128;
    const int hbase = hblk * 32;

    // ---- weights (128 x 704 half) into swizzled smem, once ----
    const __half* Bg = g_Wc + (size_t)(hblk*128)*KPAD;
    for (int i = tid; i < 128*NCHUNK*8; i += 256){
        const int r = i / (NCHUNK*8);
        const int rem = i - r*(NCHUNK*8);
        const int c = rem >> 3, j = rem & 7;
        cpasync16(Wsm + c*16384 + swz((uint32_t)r*128 + j*16),
                  Bg + (size_t)r*KPAD + c*64 + j*8);
    }
    if (tid < 128) sbias[tid] = g_bc[hblk*128 + tid];
    cp_commit();                                       // group: W

    auto fillA = [&](int chunk, int stage, const __half* Ag){
        char* dst = Asm + stage*16384;
        const __half* src = Ag + chunk*64;
        #pragma unroll
        for (int p = 0; p < 4; ++p){
            const int idx = tid + p*256;
            const int r = idx >> 3, j = idx & 7;
            cpasync16(dst + swz((uint32_t)r*128 + j*16), src + (size_t)r*KPAD + j*8);
        }
        cp_commit();
    };

    // prologue: step 0 chunks 8,9 -> stages 0,1
    {
        const __half* Ag0 = g_hx + (size_t)mbase*KPAD;
        fillA(8, 0, Ag0);
        fillA(9, 1, Ag0);
    }

    float c_reg[2][2][4];
    #pragma unroll
    for (int a=0;a<2;a++) for (int b=0;b<2;b++) for (int e=0;e<4;e++) c_reg[a][b][e]=0.f;

    const int gl = lane >> 2, tl = lane & 3;
    int stg = 0;   // stage of chunk being computed this iteration

    for (int t = 0; t < TT; ++t){
        const __half* Ag  = g_hx + (size_t)t*SLOT + (size_t)mbase*KPAD;
        const __half* Agn = g_hx + (size_t)(t+1)*SLOT + (size_t)mbase*KPAD;

        float acc[2][4][2][4];
        #pragma unroll
        for (int a=0;a<2;a++) for (int b=0;b<4;b++) for (int c=0;c<2;c++)
            #pragma unroll
            for (int d=0;d<4;d++) acc[a][b][c][d]=0.f;

        for (int q = 0; q < NCHUNK; ++q){
            if (t == TT-1 && q == NCHUNK-1) cp_wait<0>(); else cp_wait<1>();
            __syncthreads();

            // issue fill for iteration q+2 (stage (stg+2)%3)
            if (!(t == TT-1 && q >= 9)){
                const int fstage = (stg + 2 >= 3) ? stg - 1 : stg + 2;
                if (q == 0){
                    fillA(10, fstage, Ag);
                } else if (q <= 8){
                    if (q == 1 && t > 0){
                        // wait for all 16 producers of this m-group to publish step t h
                        const unsigned* fp = &g_flag[mgrp][0];
                        unsigned ok;
                        do {
                            unsigned f0,f1,f2,f3,f4,f5,f6,f7;
                            asm volatile("ld.relaxed.gpu.v4.u32 {%0,%1,%2,%3}, [%4];"
                                : "=r"(f0),"=r"(f1),"=r"(f2),"=r"(f3) : "l"(fp));
                            asm volatile("ld.relaxed.gpu.v4.u32 {%0,%1,%2,%3}, [%4];"
                                : "=r"(f4),"=r"(f5),"=r"(f6),"=r"(f7) : "l"(fp+4));
                            unsigned g0,g1,g2,g3,g4,g5,g6,g7;
                            asm volatile("ld.relaxed.gpu.v4.u32 {%0,%1,%2,%3}, [%4];"
                                : "=r"(g0),"=r"(g1),"=r"(g2),"=r"(g3) : "l"(fp+8));
                            asm volatile("ld.relaxed.gpu.v4.u32 {%0,%1,%2,%3}, [%4];"
                                : "=r"(g4),"=r"(g5),"=r"(g6),"=r"(g7) : "l"(fp+12));
                            unsigned mn = min(min(min(f0,f1),min(f2,f3)), min(min(f4,f5),min(f6,f7)));
                            mn = min(mn, min(min(min(g0,g1),min(g2,g3)), min(min(g4,g5),min(g6,g7))));
                            ok = (mn >= (unsigned)t);
                        } while (!ok);
                        __threadfence();
                    }
                    fillA(q-1, fstage, Ag);            // h chunks 0..7 of step t
                } else {
                    fillA(q-1, fstage, Agn);           // chunks 8,9 of step t+1 (seq only)
                }
            }

            // compute chunk order[q] from stage stg
            const int c = (q < 3) ? q + 8 : q - 3;
            const char* Wc = Wsm + c*16384;
            const char* Ac = Asm + stg*16384;
            #pragma unroll
            for (int kk = 0; kk < 4; ++kk){
                uint32_t af[2][4];
                #pragma unroll
                for (int mf = 0; mf < 2; ++mf){
                    const uint32_t off = (uint32_t)(wm*32 + mf*16 + (lane&15))*128
                                       + (uint32_t)(kk*16 + ((lane>>4)<<3))*2;
                    ldm_x4(af[mf], Ac + swz(off));
                }
                uint32_t bf[4][4];
                #pragma unroll
                for (int g = 0; g < 4; ++g){
                    const uint32_t off = (uint32_t)(g*32 + wn*16 + (lane&7) + ((lane>>4)&1)*8)*128
                                       + (uint32_t)(kk*16 + ((lane>>3)&1)*8)*2;
                    ldm_x4(bf[g], Wc + swz(off));
                }
                #pragma unroll
                for (int mf = 0; mf < 2; ++mf)
                    #pragma unroll
                    for (int g = 0; g < 4; ++g){
                        mma_f16(acc[mf][g][0], af[mf], bf[g] + 0);
                        mma_f16(acc[mf][g][1], af[mf], bf[g] + 2);
                    }
            }
            stg = (stg + 1 >= 3) ? 0 : stg + 1;
        }

        // epilogue: gates -> c (regs) -> h (half) into slot t+1
        __half* h_out = g_hx + (size_t)(t+1)*SLOT;
        #pragma unroll
        for (int mf = 0; mf < 2; ++mf){
            #pragma unroll
            for (int nf = 0; nf < 2; ++nf){
                const int hloc0 = wn*16 + nf*8 + tl*2;
                #pragma unroll
                for (int rr = 0; rr < 2; ++rr){
                    const int row = mbase + wm*32 + mf*16 + gl + rr*8;
                    float hv[2];
                    #pragma unroll
                    for (int j = 0; j < 2; ++j){
                        const int e = rr*2 + j;
                        const int hl = hloc0 + j;
                        const float iv = acc[mf][0][nf][e] + sbias[hl];
                        const float fv = acc[mf][1][nf][e] + sbias[32 + hl];
                        const float gv = acc[mf][2][nf][e] + sbias[64 + hl];
                        const float ov = acc[mf][3][nf][e] + sbias[96 + hl];
                        const float cn = sigmf(fv)*c_reg[mf][nf][e] + sigmf(iv)*tanhfast(gv);
                        c_reg[mf][nf][e] = cn;
                        hv[j] = sigmf(ov)*tanhfast(cn);
                    }
                    *(__half2*)(h_out + (size_t)row*KPAD + hbase + hloc0) =
                        __halves2half2(__float2half(hv[0]), __float2half(hv[1]));
                }
            }
        }

        // publish h for step t+1 consumers
        __syncthreads();
        if (tid == 0){
            __threadfence();
            asm volatile("st.relaxed.gpu.u32 [%0], %1;"
                :: "l"(&g_flag[mgrp][hblk]), "r"((unsigned)(t+1)) : "memory");
        }
    }

    // reset flags for the next replay (last block to finish)
    __syncthreads();
    if (tid == 0){
        const unsigned d = atomicAdd(&g_done, 1u);
        if (d == 127u){
            for (int i = 0; i < 8; ++i)
                for (int j = 0; j < 16; ++j) g_flag[i][j] = 0u;
            g_done = 0u;
            __threadfence();
        }
    }
}

// ==================== Kernel 4: final linear over sigmoid(hs) ========================
__global__ __launch_bounds__(256) void final_kernel(
    const float* __restrict__ linW, const float* __restrict__ linb,
    float* __restrict__ outp)
{
    const int b = blockIdx.x, tid = threadIdx.x;
    float acc[4] = {0,0,0,0};
    for (int idx = tid; idx < TT*HHc; idx += 256){
        const int tq = idx >> 9, h = idx & 511;
        const float v = sigmf(__half2float(g_hx[(size_t)(tq+1)*SLOT + (size_t)b*KPAD + h]));
        #pragma unroll
        for (int o = 0; o < 4; ++o) acc[o] += v * linW[(size_t)o*(TT*HHc) + idx];
    }
    __shared__ float red[256];
    #pragma unroll
    for (int o = 0; o < 4; ++o){
        red[tid] = acc[o]; __syncthreads();
        for (int st = 128; st > 0; st >>= 1){
            if (tid < st) red[tid] += red[tid+st];
            __syncthreads();
        }
        if (tid == 0) outp[b*4 + o] = sigmf(red[0] + linb[o]);
        __syncthreads();
    }
}

// =====================================================================================
extern "C" void kernel_launch(void* const* d_in, const int* in_sizes, int n_in,
                              void* d_out, int out_size)
{
    const float* x     = (const float*)d_in[0];
    const float* ea    = (const float*)d_in[1];
    const float* cw    = (const float*)d_in[2];
    const float* cb    = (const float*)d_in[3];
    const float* gamma = (const float*)d_in[4];
    const float* beta  = (const float*)d_in[5];
    const float* Wih   = (const float*)d_in[6];
    const float* Whh   = (const float*)d_in[7];
    const float* bih   = (const float*)d_in[8];
    const float* bhh   = (const float*)d_in[9];
    const float* linW  = (const float*)d_in[10];
    const float* linb  = (const float*)d_in[11];
    const int*   ei    = (const int*)  d_in[12];
    float* outp = (float*)d_out;

    cudaFuncSetAttribute(lstm_persist_kernel,
        cudaFuncAttributeMaxDynamicSharedMemorySize, SMEM_SZ);

    pack_kernel<<<1024, 256>>>(Wih, Whh, bih, bhh);
    cheb_kernel<<<NGRAPH/8, 256>>>(x, ea, ei, cw, cb);
    bn_kernel<<<NB, 256>>>(gamma, beta);
    lstm_persist_kernel<<<dim3(16, 8), 256, SMEM_SZ>>>();
    final_kernel<<<NB, 256>>>(linW, linb, outp);
}

// round 6
// speedup vs baseline: 2.8698x; 1.0242x over previous
#include <cuda_runtime.h>
#include <cuda_fp16.h>
#include <cstdint>

#define NB   1024
#define TT   48
#define NPGc 32
#define FFc  5
#define HHc  512
#define EPGc 256
#define NTOT (NB*TT*NPGc)
#define ETOT (NB*TT*EPGc)
#define NGRAPH (NB*TT)
#define SEQW 160
#define TSEQ (TT*SEQW)
#define KTOT 672
#define KPAD 672                   // 10 chunks of 64 + 1 half chunk (32)
#define SLOT ((size_t)NB*KPAD)
#define NCHUNK 11

// dynamic smem layout for lstm kernel
#define SOFF_BIAS 0                // 512 B
#define SOFF_A    1024             // 3 stages x 16384
#define SOFF_W    (1024 + 3*16384) // 11 chunks x 16384 (chunk 10 half-used)
#define SMEM_SZ   (SOFF_W + NCHUNK*16384)   // 230400 B

// ---------------- static device scratch --------------------------------------------
__device__ __align__(128) float  g_y  [NTOT*FFc];
__device__ __align__(128) __half g_hx [49*NB*KPAD];   // [t][B][ h(512) | seq(160) ]
__device__ __align__(128) __half g_Wc [4*HHc*KPAD];   // packed [Whh|Wih] half (row-permuted)
__device__ __align__(128) float  g_bc [4*HHc];
__device__ __align__(128) float  g_stat[NB*16];       // [b][0..4]=sum, [b][8..12]=sumsq
__device__ __align__(128) unsigned g_flag[8][16];     // [mgrp][hblk] step counters
__device__ unsigned g_done = 0;

__device__ __forceinline__ float sigmf(float x){ return __fdividef(1.f, 1.f + __expf(-x)); }
__device__ __forceinline__ float tanhfast(float x){
    const float e = __expf(2.f*x);
    return 1.f - __fdividef(2.f, e + 1.f);
}

__device__ __forceinline__ void cpasync16(void* dst, const void* src){
    uint32_t d = (uint32_t)__cvta_generic_to_shared(dst);
    asm volatile("cp.async.cg.shared.global [%0], [%1], 16;\n" :: "r"(d), "l"(src));
}
__device__ __forceinline__ void cp_commit(){ asm volatile("cp.async.commit_group;\n"); }
template<int N> __device__ __forceinline__ void cp_wait(){
    asm volatile("cp.async.wait_group %0;\n" :: "n"(N));
}
__device__ __forceinline__ void ldm_x4(uint32_t* r, const void* p){
    uint32_t a = (uint32_t)__cvta_generic_to_shared(p);
    asm volatile("ldmatrix.sync.aligned.m8n8.x4.shared.b16 {%0,%1,%2,%3}, [%4];"
        : "=r"(r[0]), "=r"(r[1]), "=r"(r[2]), "=r"(r[3]) : "r"(a));
}
__device__ __forceinline__ void mma_f16(float* d, const uint32_t* a, const uint32_t* b){
    asm volatile("mma.sync.aligned.m16n8k16.row.col.f32.f16.f16.f32 "
        "{%0,%1,%2,%3}, {%4,%5,%6,%7}, {%8,%9}, {%0,%1,%2,%3};"
        : "+f"(d[0]), "+f"(d[1]), "+f"(d[2]), "+f"(d[3])
        : "r"(a[0]), "r"(a[1]), "r"(a[2]), "r"(a[3]), "r"(b[0]), "r"(b[1]));
}
__device__ __forceinline__ uint32_t swz(uint32_t off){ return off ^ ((off >> 3) & 0x70); }

// ==================== Kernel 0: pack weights (+bias) to half; zero stats =============
__global__ __launch_bounds__(256) void pack_kernel(
    const float* __restrict__ Wih, const float* __restrict__ Whh,
    const float* __restrict__ bih, const float* __restrict__ bhh)
{
    int idx = blockIdx.x*256 + threadIdx.x;
    if (idx < NB*16) g_stat[idx] = 0.f;
    const int total = 4*HHc*KPAD;
    for (; idx < total; idx += gridDim.x*256){
        const int R = idx / KPAD, k = idx - R*KPAD;
        const int hblk = R >> 7, within = R & 127;
        const int g = within >> 5, hloc = within & 31;
        const int p = g*HHc + hblk*32 + hloc;
        const float v = (k < HHc) ? Whh[(size_t)p*HHc + k] : Wih[(size_t)p*SEQW + (k-HHc)];
        g_Wc[idx] = __float2half(v);
        if (k == 0) g_bc[R] = bih[p] + bhh[p];
    }
}

// ==================== Kernel 1: ChebConv — dense L per graph, warp per graph =========
__global__ __launch_bounds__(256) void cheb_kernel(
    const float* __restrict__ x, const float* __restrict__ ea,
    const int* __restrict__ ei, const float* __restrict__ cw,
    const float* __restrict__ cb)
{
    __shared__ float sL[8][32*33];     // dense L~, stride 33 (bank-conflict-free)
    __shared__ float sx[8][160], st1[8][160], sdeg[8][32];
    const int tid = threadIdx.x, lane = tid & 31, wid = tid >> 5;
    const int g  = blockIdx.x*8 + wid;
    const int nb = g * NPGc;
    const int b  = g / TT;
    float* L   = sL[wid];
    float* SX  = sx[wid];
    float* ST1 = st1[wid];
    float* SD  = sdeg[wid];

    #pragma unroll
    for (int i = 0; i < 33; ++i) L[i*32 + lane] = 0.f;
    #pragma unroll
    for (int r = 0; r < 5; ++r) SX[r*32 + lane] = x[(size_t)nb*FFc + r*32 + lane];
    SD[lane] = 0.f;
    __syncwarp();

    int es[8], ed[8];
    float ew[8];
    #pragma unroll
    for (int r = 0; r < 8; ++r){
        const int e = g*EPGc + r*32 + lane;
        es[r] = ei[e]        - nb;
        ed[r] = ei[ETOT + e] - nb;
        ew[r] = ea[e];
        atomicAdd(&SD[es[r]], ew[r]);
    }
    __syncwarp();
    {
        float dv = SD[lane];
        dv = (dv > 0.f) ? rsqrtf(dv) : 0.f;
        __syncwarp();
        SD[lane] = dv;
    }
    __syncwarp();
    #pragma unroll
    for (int r = 0; r < 8; ++r){
        const float nrm = -SD[es[r]] * ew[r] * SD[ed[r]];
        atomicAdd(&L[ed[r]*33 + es[r]], nrm);
    }
    __syncwarp();

    // T1 row (lane): t1 = L~ x
    float t1f[5] = {0,0,0,0,0};
    #pragma unroll 4
    for (int s = 0; s < 32; ++s){
        const float l = L[lane*33 + s];
        #pragma unroll
        for (int f = 0; f < 5; ++f) t1f[f] += l * SX[s*5 + f];
    }
    #pragma unroll
    for (int f = 0; f < 5; ++f) ST1[lane*5 + f] = t1f[f];
    __syncwarp();

    // T2 row: t2 = 2*(L~ t1) - x
    float t2f[5] = {0,0,0,0,0};
    #pragma unroll 4
    for (int s = 0; s < 32; ++s){
        const float l = L[lane*33 + s];
        #pragma unroll
        for (int f = 0; f < 5; ++f) t2f[f] += l * ST1[s*5 + f];
    }
    float x0[5];
    #pragma unroll
    for (int f = 0; f < 5; ++f){
        x0[f] = SX[lane*5 + f];
        t2f[f] = 2.f*t2f[f] - x0[f];
    }

    // output GEMM + BN stats
    float o[5], s2[5];
    #pragma unroll
    for (int j = 0; j < 5; ++j) o[j] = __ldg(&cb[j]);
    #pragma unroll
    for (int i = 0; i < 5; ++i){
        #pragma unroll
        for (int j = 0; j < 5; ++j)
            o[j] += x0[i]*__ldg(&cw[i*5+j]) + t1f[i]*__ldg(&cw[25+i*5+j]) + t2f[i]*__ldg(&cw[50+i*5+j]);
    }
    #pragma unroll
    for (int j = 0; j < 5; ++j){
        g_y[(size_t)nb*FFc + lane*FFc + j] = o[j];
        s2[j] = o[j]*o[j];
    }
    float s1[5];
    #pragma unroll
    for (int j = 0; j < 5; ++j) s1[j] = o[j];
    #pragma unroll
    for (int off = 16; off; off >>= 1){
        #pragma unroll
        for (int j = 0; j < 5; ++j){
            s1[j] += __shfl_xor_sync(0xffffffffu, s1[j], off);
            s2[j] += __shfl_xor_sync(0xffffffffu, s2[j], off);
        }
    }
    if (lane == 0){
        #pragma unroll
        for (int j = 0; j < 5; ++j){
            atomicAdd(&g_stat[b*16 + j],     s1[j]);
            atomicAdd(&g_stat[b*16 + 8 + j], s2[j]);
        }
    }
}

// ==================== Kernel 2: BN transform (stats precomputed) =====================
__global__ __launch_bounds__(256) void bn_kernel(
    const float* __restrict__ gamma, const float* __restrict__ beta)
{
    const int b = blockIdx.x, tid = threadIdx.x;
    __shared__ float sc[5], sh[5];
    if (tid < 5){
        const float inv = 1.f / (float)(TT*NPGc);
        const float mean = g_stat[b*16 + tid] * inv;
        const float var  = g_stat[b*16 + 8 + tid] * inv - mean*mean;
        const float scl  = gamma[tid] * rsqrtf(var + 1e-5f);
        sc[tid] = scl; sh[tid] = beta[tid] - mean*scl;
    }
    __syncthreads();
    const float* yb = g_y + (size_t)b * TSEQ;
    __half2* hz = (__half2*)(g_hx + (size_t)b*KPAD);
    for (int j = tid; j < HHc/2; j += 256) hz[j] = __half2half2(__float2half(0.f));
    for (int nidx = tid; nidx < TT*NPGc; nidx += 256){
        const int t = nidx >> 5, node = nidx & 31;
        const float* p = yb + nidx*FFc;
        __half* ob = g_hx + (size_t)t*SLOT + (size_t)b*KPAD + HHc + node*FFc;
        #pragma unroll
        for (int f = 0; f < 5; ++f) ob[f] = __float2half(sigmf(p[f]*sc[f] + sh[f]));
    }
}

// ==================== Kernel 3: persistent LSTM, flag-synced =========================
__global__ __launch_bounds__(256, 1) void lstm_persist_kernel()
{
    extern __shared__ char smem[];
    float* sbias = (float*)(smem + SOFF_BIAS);
    char*  Asm   = smem + SOFF_A;
    char*  Wsm   = smem + SOFF_W;

    const int tid  = threadIdx.x;
    const int lane = tid & 31, warp = tid >> 5;
    const int wm = warp >> 1, wn = warp & 1;          // 4 x 2 warp grid
    const int hblk  = blockIdx.x;                     // 16
    const int mgrp  = blockIdx.y;                     // 8
    const int mbase = mgrp * 128;
    const int hbase = hblk * 32;

    // ---- weights (128 x 672 half) into swizzled smem, once ----
    const __half* Bg = g_Wc + (size_t)(hblk*128)*KPAD;
    for (int i = tid; i < 128*84; i += 256){          // 84 x 16B pieces per row
        const int r = i / 84, p = i - r*84;
        const int ch = p >> 3, jj = p & 7;
        cpasync16(Wsm + ch*16384 + swz((uint32_t)r*128 + jj*16),
                  Bg + (size_t)r*KPAD + ch*64 + jj*8);
    }
    if (tid < 128) sbias[tid] = g_bc[hblk*128 + tid];
    cp_commit();                                       // group: W

    // ---- precomputed fill addressing (per thread) ----
    uint32_t dstoff[4], srcoff[4];
    bool jlow[4];
    #pragma unroll
    for (int p = 0; p < 4; ++p){
        const int idx = tid + p*256;
        const int r = idx >> 3, j = idx & 7;
        dstoff[p] = swz((uint32_t)r*128 + j*16);
        srcoff[p] = (uint32_t)r*KPAD + j*8;
        jlow[p] = (j < 4);
    }
    auto fillA = [&](int chunk, int stage, const __half* Ag){
        char* dst = Asm + stage*16384;
        const __half* src = Ag + chunk*64;
        if (chunk != 10){
            #pragma unroll
            for (int p = 0; p < 4; ++p) cpasync16(dst + dstoff[p], src + srcoff[p]);
        } else {
            #pragma unroll
            for (int p = 0; p < 4; ++p) if (jlow[p]) cpasync16(dst + dstoff[p], src + srcoff[p]);
        }
        cp_commit();
    };

    // prologue: step 0 chunks 8,9 -> stages 0,1
    {
        const __half* Ag0 = g_hx + (size_t)mbase*KPAD;
        fillA(8, 0, Ag0);
        fillA(9, 1, Ag0);
    }

    float c_reg[2][2][4];
    #pragma unroll
    for (int a=0;a<2;a++) for (int b=0;b<2;b++) for (int e=0;e<4;e++) c_reg[a][b][e]=0.f;

    const int gl = lane >> 2, tl = lane & 3;
    int stg = 0;

    for (int t = 0; t < TT; ++t){
        const __half* Ag  = g_hx + (size_t)t*SLOT + (size_t)mbase*KPAD;
        const __half* Agn = g_hx + (size_t)(t+1)*SLOT + (size_t)mbase*KPAD;

        float acc[2][4][2][4];
        #pragma unroll
        for (int a=0;a<2;a++) for (int b=0;b<4;b++) for (int c=0;c<2;c++)
            #pragma unroll
            for (int d=0;d<4;d++) acc[a][b][c][d]=0.f;

        for (int q = 0; q < NCHUNK; ++q){
            if (t == TT-1 && q == NCHUNK-1) cp_wait<0>(); else cp_wait<1>();
            __syncthreads();

            if (!(t == TT-1 && q >= 9)){
                const int fstage = (stg + 2 >= 3) ? stg - 1 : stg + 2;
                if (q == 0){
                    fillA(10, fstage, Ag);
                } else if (q <= 8){
                    if (q == 1 && t > 0){
                        const unsigned* fp = &g_flag[mgrp][0];
                        unsigned ok;
                        do {
                            unsigned f0,f1,f2,f3,f4,f5,f6,f7;
                            asm volatile("ld.relaxed.gpu.v4.u32 {%0,%1,%2,%3}, [%4];"
                                : "=r"(f0),"=r"(f1),"=r"(f2),"=r"(f3) : "l"(fp));
                            asm volatile("ld.relaxed.gpu.v4.u32 {%0,%1,%2,%3}, [%4];"
                                : "=r"(f4),"=r"(f5),"=r"(f6),"=r"(f7) : "l"(fp+4));
                            unsigned g0,g1,g2,g3,g4,g5,g6,g7;
                            asm volatile("ld.relaxed.gpu.v4.u32 {%0,%1,%2,%3}, [%4];"
                                : "=r"(g0),"=r"(g1),"=r"(g2),"=r"(g3) : "l"(fp+8));
                            asm volatile("ld.relaxed.gpu.v4.u32 {%0,%1,%2,%3}, [%4];"
                                : "=r"(g4),"=r"(g5),"=r"(g6),"=r"(g7) : "l"(fp+12));
                            unsigned mn = min(min(min(f0,f1),min(f2,f3)), min(min(f4,f5),min(f6,f7)));
                            mn = min(mn, min(min(min(g0,g1),min(g2,g3)), min(min(g4,g5),min(g6,g7))));
                            ok = (mn >= (unsigned)t);
                        } while (!ok);
                        __threadfence();
                    }
                    fillA(q-1, fstage, Ag);
                } else {
                    fillA(q-1, fstage, Agn);
                }
            }

            const int c = (q < 3) ? q + 8 : q - 3;
            const char* Wc = Wsm + c*16384;
            const char* Ac = Asm + stg*16384;

            #define DO_KK(kk) { \
                uint32_t af[2][4]; \
                _Pragma("unroll") \
                for (int mf = 0; mf < 2; ++mf){ \
                    const uint32_t off = (uint32_t)(wm*32 + mf*16 + (lane&15))*128 \
                                       + (uint32_t)((kk)*16 + ((lane>>4)<<3))*2; \
                    ldm_x4(af[mf], Ac + swz(off)); \
                } \
                uint32_t bf[4][4]; \
                _Pragma("unroll") \
                for (int g = 0; g < 4; ++g){ \
                    const uint32_t off = (uint32_t)(g*32 + wn*16 + (lane&7) + ((lane>>4)&1)*8)*128 \
                                       + (uint32_t)((kk)*16 + ((lane>>3)&1)*8)*2; \
                    ldm_x4(bf[g], Wc + swz(off)); \
                } \
                _Pragma("unroll") \
                for (int mf = 0; mf < 2; ++mf) \
                    _Pragma("unroll") \
                    for (int g = 0; g < 4; ++g){ \
                        mma_f16(acc[mf][g][0], af[mf], bf[g] + 0); \
                        mma_f16(acc[mf][g][1], af[mf], bf[g] + 2); \
                    } \
            }
            if (c != 10){
                DO_KK(0); DO_KK(1); DO_KK(2); DO_KK(3);
            } else {
                DO_KK(0); DO_KK(1);
            }
            #undef DO_KK
            stg = (stg + 1 >= 3) ? 0 : stg + 1;
        }

        // epilogue: gates -> c (regs) -> h (half) into slot t+1
        __half* h_out = g_hx + (size_t)(t+1)*SLOT;
        #pragma unroll
        for (int mf = 0; mf < 2; ++mf){
            #pragma unroll
            for (int nf = 0; nf < 2; ++nf){
                const int hloc0 = wn*16 + nf*8 + tl*2;
                #pragma unroll
                for (int rr = 0; rr < 2; ++rr){
                    const int row = mbase + wm*32 + mf*16 + gl + rr*8;
                    float hv[2];
                    #pragma unroll
                    for (int j = 0; j < 2; ++j){
                        const int e = rr*2 + j;
                        const int hl = hloc0 + j;
                        const float iv = acc[mf][0][nf][e] + sbias[hl];
                        const float fv = acc[mf][1][nf][e] + sbias[32 + hl];
                        const float gv = acc[mf][2][nf][e] + sbias[64 + hl];
                        const float ov = acc[mf][3][nf][e] + sbias[96 + hl];
                        const float cn = sigmf(fv)*c_reg[mf][nf][e] + sigmf(iv)*tanhfast(gv);
                        c_reg[mf][nf][e] = cn;
                        hv[j] = sigmf(ov)*tanhfast(cn);
                    }
                    *(__half2*)(h_out + (size_t)row*KPAD + hbase + hloc0) =
                        __halves2half2(__float2half(hv[0]), __float2half(hv[1]));
                }
            }
        }

        __syncthreads();
        if (tid == 0){
            __threadfence();
            asm volatile("st.relaxed.gpu.u32 [%0], %1;"
                :: "l"(&g_flag[mgrp][hblk]), "r"((unsigned)(t+1)) : "memory");
        }
    }

    __syncthreads();
    if (tid == 0){
        const unsigned d = atomicAdd(&g_done, 1u);
        if (d == 127u){
            for (int i = 0; i < 8; ++i)
                for (int j = 0; j < 16; ++j) g_flag[i][j] = 0u;
            g_done = 0u;
            __threadfence();
        }
    }
}

// ==================== Kernel 4: final linear, 4 samples per block ====================
__global__ __launch_bounds__(256) void final_kernel(
    const float* __restrict__ linW, const float* __restrict__ linb,
    float* __restrict__ outp)
{
    const int tid = threadIdx.x, lane = tid & 31, warp = tid >> 5;
    const int b0 = blockIdx.x * 4;
    float acc[4][4];
    #pragma unroll
    for (int s = 0; s < 4; ++s)
        #pragma unroll
        for (int o = 0; o < 4; ++o) acc[s][o] = 0.f;

    for (int idx = tid; idx < TT*HHc; idx += 256){
        const int tq = idx >> 9, h = idx & 511;
        const float w0 = __ldg(&linW[idx]);
        const float w1 = __ldg(&linW[TT*HHc + idx]);
        const float w2 = __ldg(&linW[2*TT*HHc + idx]);
        const float w3 = __ldg(&linW[3*TT*HHc + idx]);
        const __half* hp = g_hx + (size_t)(tq+1)*SLOT + h;
        #pragma unroll
        for (int s = 0; s < 4; ++s){
            const float v = sigmf(__half2float(hp[(size_t)(b0+s)*KPAD]));
            acc[s][0] += v*w0; acc[s][1] += v*w1;
            acc[s][2] += v*w2; acc[s][3] += v*w3;
        }
    }
    #pragma unroll
    for (int off = 16; off; off >>= 1)
        #pragma unroll
        for (int s = 0; s < 4; ++s)
            #pragma unroll
            for (int o = 0; o < 4; ++o)
                acc[s][o] += __shfl_xor_sync(0xffffffffu, acc[s][o], off);

    __shared__ float red[8][16];
    if (lane == 0){
        #pragma unroll
        for (int s = 0; s < 4; ++s)
            #pragma unroll
            for (int o = 0; o < 4; ++o) red[warp][s*4+o] = acc[s][o];
    }
    __syncthreads();
    if (tid < 16){
        float sum = 0.f;
        #pragma unroll
        for (int w = 0; w < 8; ++w) sum += red[w][tid];
        const int s = tid >> 2, o = tid & 3;
        outp[(b0 + s)*4 + o] = sigmf(sum + __ldg(&linb[o]));
    }
}

// =====================================================================================
extern "C" void kernel_launch(void* const* d_in, const int* in_sizes, int n_in,
                              void* d_out, int out_size)
{
    const float* x     = (const float*)d_in[0];
    const float* ea    = (const float*)d_in[1];
    const float* cw    = (const float*)d_in[2];
    const float* cb    = (const float*)d_in[3];
    const float* gamma = (const float*)d_in[4];
    const float* beta  = (const float*)d_in[5];
    const float* Wih   = (const float*)d_in[6];
    const float* Whh   = (const float*)d_in[7];
    const float* bih   = (const float*)d_in[8];
    const float* bhh   = (const float*)d_in[9];
    const float* linW  = (const float*)d_in[10];
    const float* linb  = (const float*)d_in[11];
    const int*   ei    = (const int*)  d_in[12];
    float* outp = (float*)d_out;

    cudaFuncSetAttribute(lstm_persist_kernel,
        cudaFuncAttributeMaxDynamicSharedMemorySize, SMEM_SZ);

    pack_kernel<<<1024, 256>>>(Wih, Whh, bih, bhh);
    cheb_kernel<<<NGRAPH/8, 256>>>(x, ea, ei, cw, cb);
    bn_kernel<<<NB, 256>>>(gamma, beta);
    lstm_persist_kernel<<<dim3(16, 8), 256, SMEM_SZ>>>();
    final_kernel<<<NB/4, 256>>>(linW, linb, outp);
}